// round 1
// baseline (speedup 1.0000x reference)
#include <cuda_runtime.h>
#include <cstdint>
#include <cstddef>

// ---------------------------------------------------------------------------
// DecayBlock (Mamba-2-style SSD block)
//   x(8,4096,1024) -> in_proj(1040x1024) -> split xi(1024) / w(16)
//   xi -> depthwise causal conv(4) + bias -> xh(b,s,16,64)
//   A = w * w_base  -> chunked SSD (chunk=64) with per-row max-normalized
//   decay weights -> y -> out_proj(1024x1024) -> out(8,4096,1024)
//
// Algebraic simplification (exact, just reassociated):
//   L[i,j]        = exp(minpref_i - S_j)           (chunk-local cumsum S)
//   decay_states  = exp(minS_chunk - S_j)
//   decay_chunk   = exp(minG_{<=z} - G_{c+1})      (chunk-total cumsum G)
// so Y_diag is a running scan, not a matmul.
// ---------------------------------------------------------------------------

namespace {
constexpr int B_  = 8;
constexpr int S_  = 4096;
constexpr int DM_ = 1024;   // d_model == d_inner
constexpr int H_  = 16;
constexpr int N_  = 64;     // head dim
constexpr int C_  = 64;     // num chunks
constexpr int E_  = 1040;   // in_proj output dim (1024 + 16)
constexpr int M_  = B_ * S_;   // 32768 tokens
}

// Scratch (allocation-free: __device__ globals)
__device__ __align__(16) float g_xw[(size_t)M_ * E_];     // in_proj output
__device__ __align__(16) float g_y[(size_t)M_ * DM_];     // ssd output
__device__ __align__(16) float g_states[B_ * H_ * C_ * N_];
__device__ float g_cnorm[B_ * H_ * C_];
__device__ float g_T[B_ * H_ * C_];
__device__ __align__(16) float g_nstates[B_ * H_ * C_ * N_];
__device__ float g_nnorm[B_ * H_ * C_];

// ---------------------------------------------------------------------------
// SGEMM (NT): C[M,N] = A[M,K] * B[N,K]^T, fp32, 128x128 tile, 256 threads,
// 8x8 per-thread microtile, BK=16.
// FIRST=true : A = arg (x), C = g_xw, N bounds-checked (N=1040)
// FIRST=false: A = g_y,     C = arg (d_out), N multiple of 128
// ---------------------------------------------------------------------------
template <bool FIRST>
__global__ __launch_bounds__(256, 2)
void sgemm_nt(const float* __restrict__ Aarg, const float* __restrict__ Bw,
              float* __restrict__ Carg, int M, int N, int K)
{
    const float* A = FIRST ? Aarg : g_y;
    float*       C = FIRST ? g_xw : Carg;

    __shared__ float As[16][128];
    __shared__ float Bs[16][128];

    const int tid = threadIdx.x;
    const int m0 = blockIdx.y * 128;
    const int n0 = blockIdx.x * 128;
    const int ra = tid >> 2;           // 0..63
    const int c4 = (tid & 3) << 2;     // 0,4,8,12
    const int ty = tid >> 4;           // 0..15
    const int tx = tid & 15;           // 0..15

    float acc[8][8];
#pragma unroll
    for (int i = 0; i < 8; i++)
#pragma unroll
        for (int j = 0; j < 8; j++) acc[i][j] = 0.f;

    for (int k0 = 0; k0 < K; k0 += 16) {
#pragma unroll
        for (int mo = 0; mo < 128; mo += 64) {
            float4 v = *reinterpret_cast<const float4*>(
                &A[(size_t)(m0 + ra + mo) * K + k0 + c4]);
            As[c4 + 0][ra + mo] = v.x;
            As[c4 + 1][ra + mo] = v.y;
            As[c4 + 2][ra + mo] = v.z;
            As[c4 + 3][ra + mo] = v.w;
        }
#pragma unroll
        for (int no = 0; no < 128; no += 64) {
            const int nn = n0 + ra + no;
            float4 v = make_float4(0.f, 0.f, 0.f, 0.f);
            if (!FIRST || nn < N)
                v = *reinterpret_cast<const float4*>(&Bw[(size_t)nn * K + k0 + c4]);
            Bs[c4 + 0][ra + no] = v.x;
            Bs[c4 + 1][ra + no] = v.y;
            Bs[c4 + 2][ra + no] = v.z;
            Bs[c4 + 3][ra + no] = v.w;
        }
        __syncthreads();
#pragma unroll
        for (int k = 0; k < 16; k++) {
            float a[8], bv[8];
            *reinterpret_cast<float4*>(&a[0])  = *reinterpret_cast<const float4*>(&As[k][ty * 8]);
            *reinterpret_cast<float4*>(&a[4])  = *reinterpret_cast<const float4*>(&As[k][ty * 8 + 4]);
            *reinterpret_cast<float4*>(&bv[0]) = *reinterpret_cast<const float4*>(&Bs[k][tx * 8]);
            *reinterpret_cast<float4*>(&bv[4]) = *reinterpret_cast<const float4*>(&Bs[k][tx * 8 + 4]);
#pragma unroll
            for (int i = 0; i < 8; i++)
#pragma unroll
                for (int j = 0; j < 8; j++)
                    acc[i][j] = fmaf(a[i], bv[j], acc[i][j]);
        }
        __syncthreads();
    }

#pragma unroll
    for (int i = 0; i < 8; i++) {
        const int row = m0 + ty * 8 + i;
#pragma unroll
        for (int j = 0; j < 8; j++) {
            const int col = n0 + tx * 8 + j;
            if (!FIRST || col < N)
                C[(size_t)row * N + col] = acc[i][j];
        }
    }
}

// ---------------------------------------------------------------------------
// K2: per-(b,h,c) chunk stats. 64 threads, thread = head-dim lane n.
// Computes conv'd x on the fly, chunk-local cumsum S, and writes
//   states_c[n] = exp(minS) * sum_j exp(-S_j) x_j[n]
//   cnorm_c     = exp(minS) * sum_j exp(-S_j)
//   T_c         = S_63
// ---------------------------------------------------------------------------
__global__ __launch_bounds__(64)
void chunk_stats_kernel(const float* __restrict__ conv_w,
                        const float* __restrict__ conv_b,
                        const float* __restrict__ w_base)
{
    const int c = blockIdx.x, h = blockIdx.y, b = blockIdx.z;
    const int n = threadIdx.x;

    __shared__ float sx[67][64];
    __shared__ float sS[64];
    __shared__ float sE[64];
    __shared__ float sMin;

    const int ch = h * 64 + n;
    const float cw0 = conv_w[ch * 4 + 0];
    const float cw1 = conv_w[ch * 4 + 1];
    const float cw2 = conv_w[ch * 4 + 2];
    const float cw3 = conv_w[ch * 4 + 3];
    const float cb  = conv_b[ch];

    const int s0 = c * 64;
    const float* xwb = g_xw + (size_t)b * S_ * E_;

    for (int r = 0; r < 67; r++) {
        const int s = s0 - 3 + r;
        sx[r][n] = (s >= 0) ? xwb[(size_t)s * E_ + h * 64 + n] : 0.f;
    }
    // A values for this chunk (thread n loads token n of the chunk)
    sS[n] = xwb[(size_t)(s0 + n) * E_ + 1024 + h] * w_base[h];
    __syncthreads();

    if (n == 0) {
        float run = 0.f, mn = 3.4e38f;
        for (int i = 0; i < 64; i++) {
            run += sS[i];
            sS[i] = run;
            mn = fminf(mn, run);
        }
        sMin = mn;
    }
    __syncthreads();
    sE[n] = __expf(-sS[n]);
    __syncthreads();

    float r = 0.f, rn = 0.f;
#pragma unroll 4
    for (int i = 0; i < 64; i++) {
        const float e  = sE[i];
        const float xv = cb + cw0 * sx[i][n] + cw1 * sx[i + 1][n]
                            + cw2 * sx[i + 2][n] + cw3 * sx[i + 3][n];
        r  = fmaf(e, xv, r);
        rn += e;
    }

    const float sc  = __expf(sMin);
    const int   idx = (b * H_ + h) * C_ + c;
    g_states[idx * N_ + n] = sc * r;
    if (n == 0) {
        g_cnorm[idx] = sc * rn;
        g_T[idx]     = sS[63];
    }
}

// ---------------------------------------------------------------------------
// K3: per-(b,h) cross-chunk scan. W[z][c'] = exp(minG_{<=z} - G_{c'+1}), c'<z.
// ---------------------------------------------------------------------------
__global__ __launch_bounds__(64)
void chunk_scan_kernel()
{
    const int h = blockIdx.x, b = blockIdx.y;
    const int tid = threadIdx.x;

    __shared__ float G[65];
    __shared__ float MP[64];
    __shared__ float W[64][64];
    __shared__ float st[64][64];
    __shared__ float cn[64];

    const int base = (b * H_ + h) * C_;
    for (int c = 0; c < 64; c++) st[c][tid] = g_states[(base + c) * N_ + tid];
    cn[tid] = g_cnorm[base + tid];
    __syncthreads();

    if (tid == 0) {
        float run = 0.f;
        G[0] = 0.f;
        for (int c = 0; c < 64; c++) { run += g_T[base + c]; G[c + 1] = run; }
        float mn = 3.4e38f;
        for (int z = 0; z < 64; z++) { mn = fminf(mn, G[z]); MP[z] = mn; }
    }
    __syncthreads();

    for (int idx = tid; idx < 4096; idx += 64) {
        const int z = idx >> 6, cp = idx & 63;
        W[z][cp] = (cp < z) ? __expf(MP[z] - G[cp + 1]) : 0.f;
    }
    __syncthreads();

    for (int z = 0; z < 64; z++) {
        float accv = 0.f;
        for (int cp = 0; cp < z; cp++) accv = fmaf(W[z][cp], st[cp][tid], accv);
        g_nstates[(base + z) * N_ + tid] = accv;
    }
    float accn = 0.f;
    for (int cp = 0; cp < tid; cp++) accn = fmaf(W[tid][cp], cn[cp], accn);
    g_nnorm[base + tid] = accn;
}

// ---------------------------------------------------------------------------
// K4: per-(b,h,c) combine. Recomputes conv + cumsum scan (cheap), adds
// cross-chunk contribution, normalizes, writes y.
//   Y[i]    = exp(minpref_i)*r_i + exp(S_i - maxS)*nstates
//   norm[i] = exp(minpref_i)*rn_i + exp(S_i - maxS)*nnorm
// ---------------------------------------------------------------------------
__global__ __launch_bounds__(64)
void combine_kernel(const float* __restrict__ conv_w,
                    const float* __restrict__ conv_b,
                    const float* __restrict__ w_base)
{
    const int c = blockIdx.x, h = blockIdx.y, b = blockIdx.z;
    const int n = threadIdx.x;

    __shared__ float sx[67][64];
    __shared__ float sS[64];
    __shared__ float sMP[64];
    __shared__ float sE[64], sEMP[64], sSDO[64];
    __shared__ float sMax;

    const int ch = h * 64 + n;
    const float cw0 = conv_w[ch * 4 + 0];
    const float cw1 = conv_w[ch * 4 + 1];
    const float cw2 = conv_w[ch * 4 + 2];
    const float cw3 = conv_w[ch * 4 + 3];
    const float cb  = conv_b[ch];

    const int s0 = c * 64;
    const float* xwb = g_xw + (size_t)b * S_ * E_;

    for (int r = 0; r < 67; r++) {
        const int s = s0 - 3 + r;
        sx[r][n] = (s >= 0) ? xwb[(size_t)s * E_ + h * 64 + n] : 0.f;
    }
    sS[n] = xwb[(size_t)(s0 + n) * E_ + 1024 + h] * w_base[h];
    __syncthreads();

    if (n == 0) {
        float run = 0.f, mn = 3.4e38f, mx = -3.4e38f;
        for (int i = 0; i < 64; i++) {
            run += sS[i];
            sS[i] = run;
            mn = fminf(mn, run);
            sMP[i] = mn;
            mx = fmaxf(mx, run);
        }
        sMax = mx;
    }
    __syncthreads();
    sE[n]   = __expf(-sS[n]);
    sEMP[n] = __expf(sMP[n]);
    sSDO[n] = __expf(sS[n] - sMax);
    __syncthreads();

    const int idx = (b * H_ + h) * C_ + c;
    const float ns = g_nstates[idx * N_ + n];
    const float nn = g_nnorm[idx];

    float r = 0.f, rn = 0.f;
    float* yout = g_y + (size_t)(b * S_ + s0) * DM_ + h * 64 + n;

#pragma unroll 4
    for (int i = 0; i < 64; i++) {
        const float e  = sE[i];
        const float xv = cb + cw0 * sx[i][n] + cw1 * sx[i + 1][n]
                            + cw2 * sx[i + 2][n] + cw3 * sx[i + 3][n];
        r  = fmaf(e, xv, r);
        rn += e;
        const float emp = sEMP[i];
        const float sdo = sSDO[i];
        const float num = fmaf(sdo, ns, emp * r);
        const float den = fmaf(sdo, nn, emp * rn);
        yout[(size_t)i * DM_] = num / den;
    }
}

// ---------------------------------------------------------------------------
// Launch
// ---------------------------------------------------------------------------
extern "C" void kernel_launch(void* const* d_in, const int* in_sizes, int n_in,
                              void* d_out, int out_size)
{
    const float *x = nullptr, *ipw = nullptr, *cw = nullptr,
                *cb = nullptr, *wb = nullptr, *opw = nullptr;
    for (int i = 0; i < n_in; i++) {
        switch (in_sizes[i]) {
            case M_ * DM_:  x   = (const float*)d_in[i]; break;  // 33554432
            case E_ * DM_:  ipw = (const float*)d_in[i]; break;  // 1064960
            case DM_ * 4:   cw  = (const float*)d_in[i]; break;  // 4096
            case DM_:       cb  = (const float*)d_in[i]; break;  // 1024
            case H_:        wb  = (const float*)d_in[i]; break;  // 16
            case DM_ * DM_: opw = (const float*)d_in[i]; break;  // 1048576
        }
    }

    // K1: xw = x @ in_proj_w^T   (M=32768, N=1040, K=1024)
    sgemm_nt<true><<<dim3((E_ + 127) / 128, M_ / 128), 256>>>(
        x, ipw, nullptr, M_, E_, DM_);

    // K2: per-chunk stats
    chunk_stats_kernel<<<dim3(C_, H_, B_), 64>>>(cw, cb, wb);

    // K3: cross-chunk scan
    chunk_scan_kernel<<<dim3(H_, B_), 64>>>();

    // K4: combine -> y
    combine_kernel<<<dim3(C_, H_, B_), 64>>>(cw, cb, wb);

    // K5: out = y @ out_proj_w^T  (M=32768, N=1024, K=1024)
    sgemm_nt<false><<<dim3(DM_ / 128, M_ / 128), 256>>>(
        nullptr, opw, (float*)d_out, M_, DM_, DM_);
}

// round 2
// speedup vs baseline: 2.0855x; 2.0855x over previous
#include <cuda_runtime.h>
#include <cstdint>
#include <cstddef>

// ---------------------------------------------------------------------------
// DecayBlock (Mamba-2-style SSD block) — round 2: tf32 tensor-core GEMMs.
//   GEMM1 (xi cols, N=1024)  : mma.sync tf32
//   GEMM1 (w cols,  N=16)    : fp32 (errors here are exponentiated -> keep exact)
//   SSD scan kernels         : unchanged (fp32)
//   GEMM2 (out_proj, N=1024) : mma.sync tf32
// ---------------------------------------------------------------------------

namespace {
constexpr int B_  = 8;
constexpr int S_  = 4096;
constexpr int DM_ = 1024;   // d_model == d_inner
constexpr int H_  = 16;
constexpr int N_  = 64;     // head dim
constexpr int C_  = 64;     // num chunks
constexpr int E_  = 1040;   // in_proj output dim (1024 + 16)
constexpr int M_  = B_ * S_;   // 32768 tokens
}

// Scratch (allocation-free: __device__ globals)
__device__ __align__(16) float g_xw[(size_t)M_ * E_];     // in_proj output
__device__ __align__(16) float g_y[(size_t)M_ * DM_];     // ssd output
__device__ __align__(16) float g_states[B_ * H_ * C_ * N_];
__device__ float g_cnorm[B_ * H_ * C_];
__device__ float g_T[B_ * H_ * C_];
__device__ __align__(16) float g_nstates[B_ * H_ * C_ * N_];
__device__ float g_nnorm[B_ * H_ * C_];

__device__ __forceinline__ uint32_t f2tf(float f) {
    uint32_t u;
    asm("cvt.rna.tf32.f32 %0, %1;" : "=r"(u) : "f"(f));
    return u;
}

__device__ __forceinline__ void mma_tf32(float* c, const uint32_t* a, const uint32_t* b) {
    asm volatile(
        "mma.sync.aligned.m16n8k8.row.col.f32.tf32.tf32.f32 "
        "{%0,%1,%2,%3}, {%4,%5,%6,%7}, {%8,%9}, {%0,%1,%2,%3};\n"
        : "+f"(c[0]), "+f"(c[1]), "+f"(c[2]), "+f"(c[3])
        : "r"(a[0]), "r"(a[1]), "r"(a[2]), "r"(a[3]), "r"(b[0]), "r"(b[1]));
}

// ---------------------------------------------------------------------------
// TF32 tensor-core GEMM (NT): C[M,N] = A[M,K] * B[N,K]^T
// 128x128 block tile, BK=16, 256 threads = 8 warps (2 m x 4 n),
// warp tile 64x32, mma m16n8k8. M,N multiples of 128; K multiple of 16.
// FIRST=true : A = arg (x), C = g_xw (ldc=1040, cols 0..1023)
// FIRST=false: A = g_y,     C = arg (d_out), ldc = 1024
// ---------------------------------------------------------------------------
constexpr int TST = 136;  // smem row stride (floats): bank-conflict-free frags

template <bool FIRST>
__global__ __launch_bounds__(256)
void tgemm_nt(const float* __restrict__ Aarg, const float* __restrict__ Bw,
              float* __restrict__ Carg, int K, int ldc)
{
    const float* A = FIRST ? Aarg : g_y;
    float*       C = FIRST ? g_xw : Carg;

    __shared__ uint32_t As[16 * TST];
    __shared__ uint32_t Bs[16 * TST];

    const int tid  = threadIdx.x;
    const int lane = tid & 31;
    const int warp = tid >> 5;
    const int wm   = warp & 1;       // 0..1 -> m offset wm*64
    const int wn   = warp >> 1;      // 0..3 -> n offset wn*32

    const int m0 = blockIdx.y * 128;
    const int n0 = blockIdx.x * 128;

    const int ra = tid >> 2;          // 0..63
    const int c4 = (tid & 3) << 2;    // 0,4,8,12

    const int grp = lane >> 2;        // 0..7
    const int tig = lane & 3;         // 0..3

    float acc[4][4][4];
#pragma unroll
    for (int i = 0; i < 4; i++)
#pragma unroll
        for (int j = 0; j < 4; j++)
#pragma unroll
            for (int r = 0; r < 4; r++) acc[i][j][r] = 0.f;

    for (int k0 = 0; k0 < K; k0 += 16) {
        // ---- stage A, B tiles into smem as tf32 (transposed: [k][mn]) ----
#pragma unroll
        for (int mo = 0; mo < 128; mo += 64) {
            float4 v = *reinterpret_cast<const float4*>(
                &A[(size_t)(m0 + ra + mo) * K + k0 + c4]);
            As[(c4 + 0) * TST + ra + mo] = f2tf(v.x);
            As[(c4 + 1) * TST + ra + mo] = f2tf(v.y);
            As[(c4 + 2) * TST + ra + mo] = f2tf(v.z);
            As[(c4 + 3) * TST + ra + mo] = f2tf(v.w);
        }
#pragma unroll
        for (int no = 0; no < 128; no += 64) {
            float4 v = *reinterpret_cast<const float4*>(
                &Bw[(size_t)(n0 + ra + no) * K + k0 + c4]);
            Bs[(c4 + 0) * TST + ra + no] = f2tf(v.x);
            Bs[(c4 + 1) * TST + ra + no] = f2tf(v.y);
            Bs[(c4 + 2) * TST + ra + no] = f2tf(v.z);
            Bs[(c4 + 3) * TST + ra + no] = f2tf(v.w);
        }
        __syncthreads();

        // ---- two k8 steps ----
#pragma unroll
        for (int ks = 0; ks < 16; ks += 8) {
            const int kA = ks + tig;
            uint32_t afr[4][4];
#pragma unroll
            for (int mt = 0; mt < 4; mt++) {
                const int m = wm * 64 + mt * 16 + grp;
                afr[mt][0] = As[kA * TST + m];
                afr[mt][1] = As[kA * TST + m + 8];
                afr[mt][2] = As[(kA + 4) * TST + m];
                afr[mt][3] = As[(kA + 4) * TST + m + 8];
            }
            uint32_t bfr[4][2];
#pragma unroll
            for (int nt = 0; nt < 4; nt++) {
                const int n = wn * 32 + nt * 8 + grp;
                bfr[nt][0] = Bs[kA * TST + n];
                bfr[nt][1] = Bs[(kA + 4) * TST + n];
            }
#pragma unroll
            for (int mt = 0; mt < 4; mt++)
#pragma unroll
                for (int nt = 0; nt < 4; nt++)
                    mma_tf32(acc[mt][nt], afr[mt], bfr[nt]);
        }
        __syncthreads();
    }

    // ---- epilogue: float2 stores (c0,c1 adjacent cols) ----
#pragma unroll
    for (int mt = 0; mt < 4; mt++) {
        const int row = m0 + wm * 64 + mt * 16 + grp;
#pragma unroll
        for (int nt = 0; nt < 4; nt++) {
            const int col = n0 + wn * 32 + nt * 8 + tig * 2;
            *reinterpret_cast<float2*>(&C[(size_t)row * ldc + col]) =
                make_float2(acc[mt][nt][0], acc[mt][nt][1]);
            *reinterpret_cast<float2*>(&C[(size_t)(row + 8) * ldc + col]) =
                make_float2(acc[mt][nt][2], acc[mt][nt][3]);
        }
    }
}

// ---------------------------------------------------------------------------
// K1b: skinny fp32 GEMM for the 16 "w" columns (exponentiated downstream ->
// must stay fp32). Each block: 128 rows x 16 cols, K=1024 in chunks of 64.
// Thread (tid%16 = col, tid/16 = rowgrp) accumulates 8 rows.
// ---------------------------------------------------------------------------
__global__ __launch_bounds__(256)
void wgemm_kernel(const float* __restrict__ x, const float* __restrict__ ipw)
{
    __shared__ float Xs[128][65];
    __shared__ float Ws[16][64];

    const int tid = threadIdx.x;
    const int col = tid & 15;
    const int rg  = tid >> 4;       // 0..15
    const int m0  = blockIdx.x * 128;

    float acc[8];
#pragma unroll
    for (int r = 0; r < 8; r++) acc[r] = 0.f;

    for (int k0 = 0; k0 < DM_; k0 += 64) {
        // load X tile: 128 rows x 64 k
        {
            const int row = tid >> 1;           // 0..127
            const int kk0 = (tid & 1) * 32;     // 0 or 32
#pragma unroll
            for (int q = 0; q < 8; q++) {
                float4 v = *reinterpret_cast<const float4*>(
                    &x[(size_t)(m0 + row) * DM_ + k0 + kk0 + q * 4]);
                Xs[row][kk0 + q * 4 + 0] = v.x;
                Xs[row][kk0 + q * 4 + 1] = v.y;
                Xs[row][kk0 + q * 4 + 2] = v.z;
                Xs[row][kk0 + q * 4 + 3] = v.w;
            }
        }
        // load W tile: 16 rows (cols of output, ipw rows 1024..1039) x 64 k
        if (tid < 256) {
            const int wr = tid >> 4;        // 0..15
            const int wk = (tid & 15) * 4;  // 0..60
            float4 v = *reinterpret_cast<const float4*>(
                &ipw[(size_t)(1024 + wr) * DM_ + k0 + wk]);
            Ws[wr][wk + 0] = v.x;
            Ws[wr][wk + 1] = v.y;
            Ws[wr][wk + 2] = v.z;
            Ws[wr][wk + 3] = v.w;
        }
        __syncthreads();

#pragma unroll 8
        for (int k = 0; k < 64; k++) {
            const float wv = Ws[col][k];
#pragma unroll
            for (int r = 0; r < 8; r++)
                acc[r] = fmaf(Xs[rg + r * 16][k], wv, acc[r]);
        }
        __syncthreads();
    }

#pragma unroll
    for (int r = 0; r < 8; r++)
        g_xw[(size_t)(m0 + rg + r * 16) * E_ + 1024 + col] = acc[r];
}

// ---------------------------------------------------------------------------
// K2: per-(b,h,c) chunk stats (fp32, unchanged).
// ---------------------------------------------------------------------------
__global__ __launch_bounds__(64)
void chunk_stats_kernel(const float* __restrict__ conv_w,
                        const float* __restrict__ conv_b,
                        const float* __restrict__ w_base)
{
    const int c = blockIdx.x, h = blockIdx.y, b = blockIdx.z;
    const int n = threadIdx.x;

    __shared__ float sx[67][64];
    __shared__ float sS[64];
    __shared__ float sE[64];
    __shared__ float sMin;

    const int ch = h * 64 + n;
    const float cw0 = conv_w[ch * 4 + 0];
    const float cw1 = conv_w[ch * 4 + 1];
    const float cw2 = conv_w[ch * 4 + 2];
    const float cw3 = conv_w[ch * 4 + 3];
    const float cb  = conv_b[ch];

    const int s0 = c * 64;
    const float* xwb = g_xw + (size_t)b * S_ * E_;

    for (int r = 0; r < 67; r++) {
        const int s = s0 - 3 + r;
        sx[r][n] = (s >= 0) ? xwb[(size_t)s * E_ + h * 64 + n] : 0.f;
    }
    sS[n] = xwb[(size_t)(s0 + n) * E_ + 1024 + h] * w_base[h];
    __syncthreads();

    if (n == 0) {
        float run = 0.f, mn = 3.4e38f;
        for (int i = 0; i < 64; i++) {
            run += sS[i];
            sS[i] = run;
            mn = fminf(mn, run);
        }
        sMin = mn;
    }
    __syncthreads();
    sE[n] = __expf(-sS[n]);
    __syncthreads();

    float r = 0.f, rn = 0.f;
#pragma unroll 4
    for (int i = 0; i < 64; i++) {
        const float e  = sE[i];
        const float xv = cb + cw0 * sx[i][n] + cw1 * sx[i + 1][n]
                            + cw2 * sx[i + 2][n] + cw3 * sx[i + 3][n];
        r  = fmaf(e, xv, r);
        rn += e;
    }

    const float sc  = __expf(sMin);
    const int   idx = (b * H_ + h) * C_ + c;
    g_states[idx * N_ + n] = sc * r;
    if (n == 0) {
        g_cnorm[idx] = sc * rn;
        g_T[idx]     = sS[63];
    }
}

// ---------------------------------------------------------------------------
// K3: per-(b,h) cross-chunk scan (unchanged).
// ---------------------------------------------------------------------------
__global__ __launch_bounds__(64)
void chunk_scan_kernel()
{
    const int h = blockIdx.x, b = blockIdx.y;
    const int tid = threadIdx.x;

    __shared__ float G[65];
    __shared__ float MP[64];
    __shared__ float W[64][64];
    __shared__ float st[64][64];
    __shared__ float cn[64];

    const int base = (b * H_ + h) * C_;
    for (int c = 0; c < 64; c++) st[c][tid] = g_states[(base + c) * N_ + tid];
    cn[tid] = g_cnorm[base + tid];
    __syncthreads();

    if (tid == 0) {
        float run = 0.f;
        G[0] = 0.f;
        for (int c = 0; c < 64; c++) { run += g_T[base + c]; G[c + 1] = run; }
        float mn = 3.4e38f;
        for (int z = 0; z < 64; z++) { mn = fminf(mn, G[z]); MP[z] = mn; }
    }
    __syncthreads();

    for (int idx = tid; idx < 4096; idx += 64) {
        const int z = idx >> 6, cp = idx & 63;
        W[z][cp] = (cp < z) ? __expf(MP[z] - G[cp + 1]) : 0.f;
    }
    __syncthreads();

    for (int z = 0; z < 64; z++) {
        float accv = 0.f;
        for (int cp = 0; cp < z; cp++) accv = fmaf(W[z][cp], st[cp][tid], accv);
        g_nstates[(base + z) * N_ + tid] = accv;
    }
    float accn = 0.f;
    for (int cp = 0; cp < tid; cp++) accn = fmaf(W[tid][cp], cn[cp], accn);
    g_nnorm[base + tid] = accn;
}

// ---------------------------------------------------------------------------
// K4: per-(b,h,c) combine -> y (unchanged).
// ---------------------------------------------------------------------------
__global__ __launch_bounds__(64)
void combine_kernel(const float* __restrict__ conv_w,
                    const float* __restrict__ conv_b,
                    const float* __restrict__ w_base)
{
    const int c = blockIdx.x, h = blockIdx.y, b = blockIdx.z;
    const int n = threadIdx.x;

    __shared__ float sx[67][64];
    __shared__ float sS[64];
    __shared__ float sMP[64];
    __shared__ float sE[64], sEMP[64], sSDO[64];
    __shared__ float sMax;

    const int ch = h * 64 + n;
    const float cw0 = conv_w[ch * 4 + 0];
    const float cw1 = conv_w[ch * 4 + 1];
    const float cw2 = conv_w[ch * 4 + 2];
    const float cw3 = conv_w[ch * 4 + 3];
    const float cb  = conv_b[ch];

    const int s0 = c * 64;
    const float* xwb = g_xw + (size_t)b * S_ * E_;

    for (int r = 0; r < 67; r++) {
        const int s = s0 - 3 + r;
        sx[r][n] = (s >= 0) ? xwb[(size_t)s * E_ + h * 64 + n] : 0.f;
    }
    sS[n] = xwb[(size_t)(s0 + n) * E_ + 1024 + h] * w_base[h];
    __syncthreads();

    if (n == 0) {
        float run = 0.f, mn = 3.4e38f, mx = -3.4e38f;
        for (int i = 0; i < 64; i++) {
            run += sS[i];
            sS[i] = run;
            mn = fminf(mn, run);
            sMP[i] = mn;
            mx = fmaxf(mx, run);
        }
        sMax = mx;
    }
    __syncthreads();
    sE[n]   = __expf(-sS[n]);
    sEMP[n] = __expf(sMP[n]);
    sSDO[n] = __expf(sS[n] - sMax);
    __syncthreads();

    const int idx = (b * H_ + h) * C_ + c;
    const float ns = g_nstates[idx * N_ + n];
    const float nn = g_nnorm[idx];

    float r = 0.f, rn = 0.f;
    float* yout = g_y + (size_t)(b * S_ + s0) * DM_ + h * 64 + n;

#pragma unroll 4
    for (int i = 0; i < 64; i++) {
        const float e  = sE[i];
        const float xv = cb + cw0 * sx[i][n] + cw1 * sx[i + 1][n]
                            + cw2 * sx[i + 2][n] + cw3 * sx[i + 3][n];
        r  = fmaf(e, xv, r);
        rn += e;
        const float emp = sEMP[i];
        const float sdo = sSDO[i];
        const float num = fmaf(sdo, ns, emp * r);
        const float den = fmaf(sdo, nn, emp * rn);
        yout[(size_t)i * DM_] = num / den;
    }
}

// ---------------------------------------------------------------------------
// Launch
// ---------------------------------------------------------------------------
extern "C" void kernel_launch(void* const* d_in, const int* in_sizes, int n_in,
                              void* d_out, int out_size)
{
    const float *x = nullptr, *ipw = nullptr, *cw = nullptr,
                *cb = nullptr, *wb = nullptr, *opw = nullptr;
    for (int i = 0; i < n_in; i++) {
        switch (in_sizes[i]) {
            case M_ * DM_:  x   = (const float*)d_in[i]; break;  // 33554432
            case E_ * DM_:  ipw = (const float*)d_in[i]; break;  // 1064960
            case DM_ * 4:   cw  = (const float*)d_in[i]; break;  // 4096
            case DM_:       cb  = (const float*)d_in[i]; break;  // 1024
            case H_:        wb  = (const float*)d_in[i]; break;  // 16
            case DM_ * DM_: opw = (const float*)d_in[i]; break;  // 1048576
        }
    }

    // K1a: xi = x @ in_proj_w[:1024]^T   (tf32 tensor cores, M=32768 N=1024 K=1024)
    tgemm_nt<true><<<dim3(DM_ / 128, M_ / 128), 256>>>(x, ipw, nullptr, DM_, E_);

    // K1b: w = x @ in_proj_w[1024:]^T    (fp32, N=16 — stays exact)
    wgemm_kernel<<<M_ / 128, 256>>>(x, ipw);

    // K2: per-chunk stats
    chunk_stats_kernel<<<dim3(C_, H_, B_), 64>>>(cw, cb, wb);

    // K3: cross-chunk scan
    chunk_scan_kernel<<<dim3(H_, B_), 64>>>();

    // K4: combine -> y
    combine_kernel<<<dim3(C_, H_, B_), 64>>>(cw, cb, wb);

    // K5: out = y @ out_proj_w^T  (tf32 tensor cores, M=32768 N=1024 K=1024)
    tgemm_nt<false><<<dim3(DM_ / 128, M_ / 128), 256>>>(
        nullptr, opw, (float*)d_out, DM_, DM_);
}

// round 3
// speedup vs baseline: 2.7292x; 1.3086x over previous
#include <cuda_runtime.h>
#include <cstdint>
#include <cstddef>

// ---------------------------------------------------------------------------
// DecayBlock (Mamba-2 SSD block) — round 3:
//   * tf32 mma GEMMs now cp.async double-buffered (latency hidden)
//   * chunk kernels use rolling conv window (no big smem -> full occupancy)
//   * chunk_scan parallelized to 256 threads
// ---------------------------------------------------------------------------

namespace {
constexpr int B_  = 8;
constexpr int S_  = 4096;
constexpr int DM_ = 1024;
constexpr int H_  = 16;
constexpr int N_  = 64;
constexpr int C_  = 64;
constexpr int E_  = 1040;
constexpr int M_  = B_ * S_;
}

__device__ __align__(16) float g_xw[(size_t)M_ * E_];
__device__ __align__(16) float g_y[(size_t)M_ * DM_];
__device__ __align__(16) float g_states[B_ * H_ * C_ * N_];
__device__ float g_cnorm[B_ * H_ * C_];
__device__ float g_T[B_ * H_ * C_];
__device__ __align__(16) float g_nstates[B_ * H_ * C_ * N_];
__device__ float g_nnorm[B_ * H_ * C_];

__device__ __forceinline__ uint32_t f2tf(float f) {
    uint32_t u;
    asm("cvt.rna.tf32.f32 %0, %1;" : "=r"(u) : "f"(f));
    return u;
}

__device__ __forceinline__ void mma_tf32(float* c, const uint32_t* a, const uint32_t* b) {
    asm volatile(
        "mma.sync.aligned.m16n8k8.row.col.f32.tf32.tf32.f32 "
        "{%0,%1,%2,%3}, {%4,%5,%6,%7}, {%8,%9}, {%0,%1,%2,%3};\n"
        : "+f"(c[0]), "+f"(c[1]), "+f"(c[2]), "+f"(c[3])
        : "r"(a[0]), "r"(a[1]), "r"(a[2]), "r"(a[3]), "r"(b[0]), "r"(b[1]));
}

__device__ __forceinline__ void cp16(void* smem, const void* gmem) {
    uint32_t s = (uint32_t)__cvta_generic_to_shared(smem);
    asm volatile("cp.async.cg.shared.global [%0], [%1], 16;\n" :: "r"(s), "l"(gmem));
}

// ---------------------------------------------------------------------------
// TF32 GEMM (NT): C[M,N] = A[M,K] * B[N,K]^T
// 128x128 tile, BK=16, 2-stage cp.async pipeline, 256 threads (8 warps, 2x4),
// warp tile 64x32, mma m16n8k8, fp32 staged in smem, cvt at fragment load.
// ---------------------------------------------------------------------------
constexpr int GLD = 20;  // smem row stride (16 + 4 pad)

template <bool FIRST>
__global__ __launch_bounds__(256)
void tgemm_nt(const float* __restrict__ Aarg, const float* __restrict__ Bw,
              float* __restrict__ Carg, int K, int ldc)
{
    const float* A = FIRST ? Aarg : g_y;
    float*       C = FIRST ? g_xw : Carg;

    __shared__ float As[2][128][GLD];
    __shared__ float Bs[2][128][GLD];

    const int tid  = threadIdx.x;
    const int lane = tid & 31;
    const int warp = tid >> 5;
    const int wm   = warp & 1;        // m offset wm*64
    const int wn   = warp >> 1;       // n offset wn*32
    const int grp  = lane >> 2;       // 0..7
    const int tig  = lane & 3;        // 0..3

    const int m0 = blockIdx.y * 128;
    const int n0 = blockIdx.x * 128;

    const int lrow = tid >> 1;        // 0..127
    const int lk   = (tid & 1) * 8;   // 0 or 8

    const float* gA = A  + (size_t)(m0 + lrow) * K + lk;
    const float* gB = Bw + (size_t)(n0 + lrow) * K + lk;

    float acc[4][4][4];
#pragma unroll
    for (int i = 0; i < 4; i++)
#pragma unroll
        for (int j = 0; j < 4; j++)
#pragma unroll
            for (int r = 0; r < 4; r++) acc[i][j][r] = 0.f;

    auto load_stage = [&](int st, int k0) {
        cp16(&As[st][lrow][lk],     gA + k0);
        cp16(&As[st][lrow][lk + 4], gA + k0 + 4);
        cp16(&Bs[st][lrow][lk],     gB + k0);
        cp16(&Bs[st][lrow][lk + 4], gB + k0 + 4);
    };

    load_stage(0, 0);
    asm volatile("cp.async.commit_group;\n" ::: "memory");

    const int NIT = K >> 4;
    for (int it = 0; it < NIT; ++it) {
        const int cur = it & 1;
        const int nxt = cur ^ 1;
        if (it + 1 < NIT) {
            load_stage(nxt, (it + 1) << 4);
            asm volatile("cp.async.commit_group;\n" ::: "memory");
            asm volatile("cp.async.wait_group 1;\n" ::: "memory");
        } else {
            asm volatile("cp.async.wait_group 0;\n" ::: "memory");
        }
        __syncthreads();

#pragma unroll
        for (int ks = 0; ks < 16; ks += 8) {
            const int kA = ks + tig;
            uint32_t afr[4][4];
#pragma unroll
            for (int mt = 0; mt < 4; mt++) {
                const int m = wm * 64 + mt * 16 + grp;
                afr[mt][0] = f2tf(As[cur][m][kA]);
                afr[mt][1] = f2tf(As[cur][m + 8][kA]);
                afr[mt][2] = f2tf(As[cur][m][kA + 4]);
                afr[mt][3] = f2tf(As[cur][m + 8][kA + 4]);
            }
            uint32_t bfr[4][2];
#pragma unroll
            for (int nt = 0; nt < 4; nt++) {
                const int n = wn * 32 + nt * 8 + grp;
                bfr[nt][0] = f2tf(Bs[cur][n][kA]);
                bfr[nt][1] = f2tf(Bs[cur][n][kA + 4]);
            }
#pragma unroll
            for (int mt = 0; mt < 4; mt++)
#pragma unroll
                for (int nt = 0; nt < 4; nt++)
                    mma_tf32(acc[mt][nt], afr[mt], bfr[nt]);
        }
        __syncthreads();
    }

#pragma unroll
    for (int mt = 0; mt < 4; mt++) {
        const int row = m0 + wm * 64 + mt * 16 + grp;
#pragma unroll
        for (int nt = 0; nt < 4; nt++) {
            const int col = n0 + wn * 32 + nt * 8 + tig * 2;
            *reinterpret_cast<float2*>(&C[(size_t)row * ldc + col]) =
                make_float2(acc[mt][nt][0], acc[mt][nt][1]);
            *reinterpret_cast<float2*>(&C[(size_t)(row + 8) * ldc + col]) =
                make_float2(acc[mt][nt][2], acc[mt][nt][3]);
        }
    }
}

// ---------------------------------------------------------------------------
// K1b: skinny fp32 GEMM for the 16 "w" columns (exact fp32).
// ---------------------------------------------------------------------------
__global__ __launch_bounds__(256)
void wgemm_kernel(const float* __restrict__ x, const float* __restrict__ ipw)
{
    __shared__ float Xs[128][65];
    __shared__ float Ws[16][64];

    const int tid = threadIdx.x;
    const int col = tid & 15;
    const int rg  = tid >> 4;
    const int m0  = blockIdx.x * 128;

    float acc[8];
#pragma unroll
    for (int r = 0; r < 8; r++) acc[r] = 0.f;

    for (int k0 = 0; k0 < DM_; k0 += 64) {
        {
            const int row = tid >> 1;
            const int kk0 = (tid & 1) * 32;
#pragma unroll
            for (int q = 0; q < 8; q++) {
                float4 v = *reinterpret_cast<const float4*>(
                    &x[(size_t)(m0 + row) * DM_ + k0 + kk0 + q * 4]);
                Xs[row][kk0 + q * 4 + 0] = v.x;
                Xs[row][kk0 + q * 4 + 1] = v.y;
                Xs[row][kk0 + q * 4 + 2] = v.z;
                Xs[row][kk0 + q * 4 + 3] = v.w;
            }
        }
        {
            const int wr = tid >> 4;
            const int wk = (tid & 15) * 4;
            if (wr < 16) {
                float4 v = *reinterpret_cast<const float4*>(
                    &ipw[(size_t)(1024 + wr) * DM_ + k0 + wk]);
                Ws[wr][wk + 0] = v.x;
                Ws[wr][wk + 1] = v.y;
                Ws[wr][wk + 2] = v.z;
                Ws[wr][wk + 3] = v.w;
            }
        }
        __syncthreads();

#pragma unroll 8
        for (int k = 0; k < 64; k++) {
            const float wv = Ws[col][k];
#pragma unroll
            for (int r = 0; r < 8; r++)
                acc[r] = fmaf(Xs[rg + r * 16][k], wv, acc[r]);
        }
        __syncthreads();
    }

#pragma unroll
    for (int r = 0; r < 8; r++)
        g_xw[(size_t)(m0 + rg + r * 16) * E_ + 1024 + col] = acc[r];
}

// ---------------------------------------------------------------------------
// K2: per-(b,h,c) chunk stats — rolling conv window, no tile smem.
// ---------------------------------------------------------------------------
__global__ __launch_bounds__(64)
void chunk_stats_kernel(const float* __restrict__ conv_w,
                        const float* __restrict__ conv_b,
                        const float* __restrict__ w_base)
{
    const int c = blockIdx.x, h = blockIdx.y, b = blockIdx.z;
    const int n = threadIdx.x;

    __shared__ float sS[64];
    __shared__ float sE[64];
    __shared__ float sMin;

    const int ch = h * 64 + n;
    const float cw0 = conv_w[ch * 4 + 0];
    const float cw1 = conv_w[ch * 4 + 1];
    const float cw2 = conv_w[ch * 4 + 2];
    const float cw3 = conv_w[ch * 4 + 3];
    const float cb  = conv_b[ch];

    const int s0 = c * 64;
    const float* xwb = g_xw + (size_t)b * S_ * E_;
    const float* xp  = xwb + (size_t)s0 * E_ + h * 64 + n;

    float xm3 = 0.f, xm2 = 0.f, xm1 = 0.f;
    if (c > 0) {
        xm3 = xp[-(ptrdiff_t)(3 * E_)];
        xm2 = xp[-(ptrdiff_t)(2 * E_)];
        xm1 = xp[-(ptrdiff_t)(1 * E_)];
    }

    sS[n] = xwb[(size_t)(s0 + n) * E_ + 1024 + h] * w_base[h];
    __syncthreads();

    if (n == 0) {
        float run = 0.f, mn = 3.4e38f;
        for (int i = 0; i < 64; i++) {
            run += sS[i];
            sS[i] = run;
            mn = fminf(mn, run);
        }
        sMin = mn;
    }
    __syncthreads();
    sE[n] = __expf(-sS[n]);
    __syncthreads();

    float r = 0.f, rn = 0.f;
#pragma unroll 4
    for (int i = 0; i < 64; i++) {
        const float x0 = xp[(size_t)i * E_];
        const float xv = cb + cw0 * xm3 + cw1 * xm2 + cw2 * xm1 + cw3 * x0;
        xm3 = xm2; xm2 = xm1; xm1 = x0;
        const float e = sE[i];
        r  = fmaf(e, xv, r);
        rn += e;
    }

    const float sc  = __expf(sMin);
    const int   idx = (b * H_ + h) * C_ + c;
    g_states[idx * N_ + n] = sc * r;
    if (n == 0) {
        g_cnorm[idx] = sc * rn;
        g_T[idx]     = sS[63];
    }
}

// ---------------------------------------------------------------------------
// K3: per-(b,h) cross-chunk scan — 256 threads (z split 4 ways).
// ---------------------------------------------------------------------------
__global__ __launch_bounds__(256)
void chunk_scan_kernel()
{
    const int h = blockIdx.x, b = blockIdx.y;
    const int tid = threadIdx.x;
    const int n  = tid & 63;
    const int zq = tid >> 6;

    __shared__ float G[65];
    __shared__ float MP[64];
    __shared__ float W[64][64];
    __shared__ float st[64][64];
    __shared__ float cn[64];

    const int base = (b * H_ + h) * C_;

    for (int idx = tid; idx < 4096; idx += 256)
        st[idx >> 6][idx & 63] = g_states[(size_t)base * N_ + idx];
    if (tid < 64) cn[tid] = g_cnorm[base + tid];
    __syncthreads();

    if (tid == 0) {
        float run = 0.f;
        G[0] = 0.f;
        for (int c = 0; c < 64; c++) { run += g_T[base + c]; G[c + 1] = run; }
        float mn = 3.4e38f;
        for (int z = 0; z < 64; z++) { mn = fminf(mn, G[z]); MP[z] = mn; }
    }
    __syncthreads();

    for (int idx = tid; idx < 4096; idx += 256) {
        const int z = idx >> 6, cp = idx & 63;
        W[z][cp] = (cp < z) ? __expf(MP[z] - G[cp + 1]) : 0.f;
    }
    __syncthreads();

    for (int z = zq; z < 64; z += 4) {
        float accv = 0.f;
        for (int cp = 0; cp < z; cp++) accv = fmaf(W[z][cp], st[cp][n], accv);
        g_nstates[(base + z) * N_ + n] = accv;
    }
    if (tid < 64) {
        float accn = 0.f;
        for (int cp = 0; cp < tid; cp++) accn = fmaf(W[tid][cp], cn[cp], accn);
        g_nnorm[base + tid] = accn;
    }
}

// ---------------------------------------------------------------------------
// K4: per-(b,h,c) combine -> y — rolling conv window.
// ---------------------------------------------------------------------------
__global__ __launch_bounds__(64)
void combine_kernel(const float* __restrict__ conv_w,
                    const float* __restrict__ conv_b,
                    const float* __restrict__ w_base)
{
    const int c = blockIdx.x, h = blockIdx.y, b = blockIdx.z;
    const int n = threadIdx.x;

    __shared__ float sS[64];
    __shared__ float sE[64], sEMP[64], sSDO[64];
    __shared__ float sMP[64];
    __shared__ float sMax;

    const int ch = h * 64 + n;
    const float cw0 = conv_w[ch * 4 + 0];
    const float cw1 = conv_w[ch * 4 + 1];
    const float cw2 = conv_w[ch * 4 + 2];
    const float cw3 = conv_w[ch * 4 + 3];
    const float cb  = conv_b[ch];

    const int s0 = c * 64;
    const float* xwb = g_xw + (size_t)b * S_ * E_;
    const float* xp  = xwb + (size_t)s0 * E_ + h * 64 + n;

    float xm3 = 0.f, xm2 = 0.f, xm1 = 0.f;
    if (c > 0) {
        xm3 = xp[-(ptrdiff_t)(3 * E_)];
        xm2 = xp[-(ptrdiff_t)(2 * E_)];
        xm1 = xp[-(ptrdiff_t)(1 * E_)];
    }

    sS[n] = xwb[(size_t)(s0 + n) * E_ + 1024 + h] * w_base[h];
    __syncthreads();

    if (n == 0) {
        float run = 0.f, mn = 3.4e38f, mx = -3.4e38f;
        for (int i = 0; i < 64; i++) {
            run += sS[i];
            sS[i] = run;
            mn = fminf(mn, run);
            sMP[i] = mn;
            mx = fmaxf(mx, run);
        }
        sMax = mx;
    }
    __syncthreads();
    sE[n]   = __expf(-sS[n]);
    sEMP[n] = __expf(sMP[n]);
    sSDO[n] = __expf(sS[n] - sMax);
    __syncthreads();

    const int idx = (b * H_ + h) * C_ + c;
    const float ns = g_nstates[idx * N_ + n];
    const float nn = g_nnorm[idx];

    float r = 0.f, rn = 0.f;
    float* yout = g_y + (size_t)(b * S_ + s0) * DM_ + h * 64 + n;

#pragma unroll 4
    for (int i = 0; i < 64; i++) {
        const float x0 = xp[(size_t)i * E_];
        const float xv = cb + cw0 * xm3 + cw1 * xm2 + cw2 * xm1 + cw3 * x0;
        xm3 = xm2; xm2 = xm1; xm1 = x0;
        const float e = sE[i];
        r  = fmaf(e, xv, r);
        rn += e;
        const float emp = sEMP[i];
        const float sdo = sSDO[i];
        const float num = fmaf(sdo, ns, emp * r);
        const float den = fmaf(sdo, nn, emp * rn);
        yout[(size_t)i * DM_] = num / den;
    }
}

// ---------------------------------------------------------------------------
// Launch
// ---------------------------------------------------------------------------
extern "C" void kernel_launch(void* const* d_in, const int* in_sizes, int n_in,
                              void* d_out, int out_size)
{
    const float *x = nullptr, *ipw = nullptr, *cw = nullptr,
                *cb = nullptr, *wb = nullptr, *opw = nullptr;
    for (int i = 0; i < n_in; i++) {
        switch (in_sizes[i]) {
            case M_ * DM_:  x   = (const float*)d_in[i]; break;
            case E_ * DM_:  ipw = (const float*)d_in[i]; break;
            case DM_ * 4:   cw  = (const float*)d_in[i]; break;
            case DM_:       cb  = (const float*)d_in[i]; break;
            case H_:        wb  = (const float*)d_in[i]; break;
            case DM_ * DM_: opw = (const float*)d_in[i]; break;
        }
    }

    // K1a: xi = x @ in_proj_w[:1024]^T (tf32 TC, pipelined)
    tgemm_nt<true><<<dim3(DM_ / 128, M_ / 128), 256>>>(x, ipw, nullptr, DM_, E_);

    // K1b: w = x @ in_proj_w[1024:]^T (fp32)
    wgemm_kernel<<<M_ / 128, 256>>>(x, ipw);

    // K2: per-chunk stats
    chunk_stats_kernel<<<dim3(C_, H_, B_), 64>>>(cw, cb, wb);

    // K3: cross-chunk scan
    chunk_scan_kernel<<<dim3(H_, B_), 256>>>();

    // K4: combine -> y
    combine_kernel<<<dim3(C_, H_, B_), 64>>>(cw, cb, wb);

    // K5: out = y @ out_proj_w^T (tf32 TC, pipelined)
    tgemm_nt<false><<<dim3(DM_ / 128, M_ / 128), 256>>>(
        nullptr, opw, (float*)d_out, DM_, DM_);
}